// round 13
// baseline (speedup 1.0000x reference)
#include <cuda_runtime.h>
#include <cuda_fp16.h>
#include <cstdint>

#define EMB   1024
#define NH    16
#define HD    64
#define BATCH 2
#define SEQ   2048
#define MTOK  (BATCH*SEQ)   // 4096
#define BHN   (BATCH*NH)    // 32

// ---------------- scratch (__device__ globals; no allocs allowed) -----------
__device__ __half g_Xhi[(size_t)MTOK*EMB], g_Xlo[(size_t)MTOK*EMB];
__device__ __half g_A[(size_t)MTOK*EMB];
__device__ __half g_Qh[(size_t)MTOK*EMB], g_Ql[(size_t)MTOK*EMB];
__device__ __half g_Kh[(size_t)MTOK*EMB];
__device__ __half g_Vh[(size_t)MTOK*EMB];
__device__ __half g_Wq[(size_t)EMB*EMB], g_Wk[(size_t)EMB*EMB];
__device__ __half g_Wv[(size_t)EMB*EMB], g_Wo[(size_t)EMB*EMB];

// ---------------- helpers ---------------------------------------------------
__device__ __forceinline__ uint32_t smem_u32(const void* p) {
    uint32_t a;
    asm("{ .reg .u64 t; cvta.to.shared.u64 t, %1; cvt.u32.u64 %0, t; }" : "=r"(a) : "l"(p));
    return a;
}
__device__ __forceinline__ void cp16(uint32_t d, const void* s) {
    asm volatile("cp.async.cg.shared.global [%0], [%1], 16;" :: "r"(d), "l"(s));
}
#define CP_COMMIT() asm volatile("cp.async.commit_group;")
#define CP_WAIT(n)  asm volatile("cp.async.wait_group %0;" :: "n"(n))

__device__ __forceinline__ void ldsm4(uint32_t (&r)[4], uint32_t a) {
    asm volatile("ldmatrix.sync.aligned.m8n8.x4.shared.b16 {%0,%1,%2,%3}, [%4];"
        : "=r"(r[0]), "=r"(r[1]), "=r"(r[2]), "=r"(r[3]) : "r"(a));
}
__device__ __forceinline__ void ldsm4t(uint32_t (&r)[4], uint32_t a) {
    asm volatile("ldmatrix.sync.aligned.m8n8.x4.trans.shared.b16 {%0,%1,%2,%3}, [%4];"
        : "=r"(r[0]), "=r"(r[1]), "=r"(r[2]), "=r"(r[3]) : "r"(a));
}
__device__ __forceinline__ void mma_h(float (&c)[4], const uint32_t (&a)[4], uint32_t b0, uint32_t b1) {
    asm("mma.sync.aligned.m16n8k16.row.col.f32.f16.f16.f32 "
        "{%0,%1,%2,%3}, {%4,%5,%6,%7}, {%8,%9}, {%0,%1,%2,%3};"
        : "+f"(c[0]), "+f"(c[1]), "+f"(c[2]), "+f"(c[3])
        : "r"(a[0]), "r"(a[1]), "r"(a[2]), "r"(a[3]), "r"(b0), "r"(b1));
}
__device__ __forceinline__ uint32_t packh(float v0, float v1) {
    __half2 h = __floats2half2_rn(v0, v1);
    return *(uint32_t*)&h;
}
__device__ __forceinline__ void split2h(float v0, float v1, uint32_t &hp, uint32_t &lp) {
    __half2 h = __floats2half2_rn(v0, v1);
    hp = *(uint32_t*)&h;
    float h0 = __half2float(__low2half(h));
    float h1 = __half2float(__high2half(h));
    lp = packh(v0 - h0, v1 - h1);
}
__device__ __forceinline__ uint32_t ex2h2(uint32_t x) {
    uint32_t r;
    asm("ex2.approx.f16x2 %0, %1;" : "=r"(r) : "r"(x));
    return r;
}
#define ONESH2 0x3C003C00u   // half2(1.0, 1.0)

// ---------------- fused fp32 -> fp16 split (X hi/lo; W hi only) --------------
__global__ __launch_bounds__(256) void split_all_kernel(
    const float* __restrict__ x,  const float* __restrict__ wq,
    const float* __restrict__ wk, const float* __restrict__ wv,
    const float* __restrict__ wo)
{
    int i = blockIdx.x * 256 + threadIdx.x;
    if (i < 524288) {
        float4 a = ((const float4*)x)[2*i];
        float4 b = ((const float4*)x)[2*i + 1];
        float v[8] = {a.x, a.y, a.z, a.w, b.x, b.y, b.z, b.w};
        uint32_t hp[4], lp[4];
        #pragma unroll
        for (int j = 0; j < 4; j++) split2h(v[2*j], v[2*j+1], hp[j], lp[j]);
        ((uint4*)g_Xhi)[i] = make_uint4(hp[0], hp[1], hp[2], hp[3]);
        ((uint4*)g_Xlo)[i] = make_uint4(lp[0], lp[1], lp[2], lp[3]);
    } else {
        int j = i - 524288;
        int w = j >> 17;
        int off = j & 131071;
        const float* src; __half* hi;
        if (w == 0)      { src = wq; hi = g_Wq; }
        else if (w == 1) { src = wk; hi = g_Wk; }
        else if (w == 2) { src = wv; hi = g_Wv; }
        else             { src = wo; hi = g_Wo; }
        float4 a = ((const float4*)src)[2*off];
        float4 b = ((const float4*)src)[2*off + 1];
        uint32_t hp[4];
        hp[0] = packh(a.x, a.y); hp[1] = packh(a.z, a.w);
        hp[2] = packh(b.x, b.y); hp[3] = packh(b.z, b.w);
        ((uint4*)hi)[off] = make_uint4(hp[0], hp[1], hp[2], hp[3]);
    }
}

// ---------------- GEMM body: 128x128 CTA, 8 warps 64x32, 2-stage, 2 CTA/SM --
#define SPAD   80
#define AL_OFF 10240
#define BH_OFF 20480
#define STG    30720
#define GEMM_SMEM (2*STG)   // 61440
#define NITER (EMB/32)      // 32

template <bool USE_LO>
__device__ __forceinline__ void gemm_body_128(
    const __half* __restrict__ Ah, const __half* __restrict__ Al,
    const __half* __restrict__ Wh,
    int m0, int n0, float (&acc)[4][4][4])
{
    extern __shared__ char sm[];
    const uint32_t smb = smem_u32(sm);
    const int tid = threadIdx.x, lane = tid & 31, wid = tid >> 5;
    const int wm = wid & 1, wn = wid >> 1;   // 2 x 4 warp grid, warp tile 64x32

    auto issue = [&](int it) {
        const int k0 = it << 5;
        const uint32_t sb = smb + (uint32_t)(it & 1) * STG;
        #pragma unroll
        for (int j = 0; j < 6; ++j) {
            int idx = tid + (j << 8);
            if (idx < 512) {
                int row = idx >> 2, seg = idx & 3;
                cp16(sb + row*SPAD + seg*16, Ah + (size_t)(m0 + row)*EMB + k0 + seg*8);
            } else if (idx < 1024) {
                if (USE_LO) {
                    int c = idx - 512, row = c >> 2, seg = c & 3;
                    cp16(sb + AL_OFF + row*SPAD + seg*16, Al + (size_t)(m0 + row)*EMB + k0 + seg*8);
                }
            } else {
                int c = idx - 1024, row = c >> 2, seg = c & 3;
                cp16(sb + BH_OFF + row*SPAD + seg*16, Wh + (size_t)(n0 + row)*EMB + k0 + seg*8);
            }
        }
        CP_COMMIT();
    };

    issue(0);
    for (int it = 0; it < NITER; ++it) {
        CP_WAIT(0);
        __syncthreads();
        if (it + 1 < NITER) issue(it + 1);
        const uint32_t sb = smb + (uint32_t)(it & 1) * STG;
        #pragma unroll
        for (int ks = 0; ks < 2; ++ks) {
            uint32_t aH[4][4], aL[4][4], bF[2][4];
            uint32_t acol = ks*32 + ((lane>>4)&1)*16;
            #pragma unroll
            for (int mf = 0; mf < 4; ++mf) {
                uint32_t row = wm*64 + mf*16 + ((lane>>3)&1)*8 + (lane&7);
                ldsm4(aH[mf], sb + row*SPAD + acol);
                if (USE_LO) ldsm4(aL[mf], sb + AL_OFF + row*SPAD + acol);
            }
            #pragma unroll
            for (int ng = 0; ng < 2; ++ng) {
                uint32_t row = wn*32 + ng*16 + ((lane>>4)&1)*8 + (lane&7);
                uint32_t col = ks*32 + ((lane>>3)&1)*16;
                ldsm4(bF[ng], sb + BH_OFF + row*SPAD + col);
            }
            #pragma unroll
            for (int ng = 0; ng < 2; ++ng)
                #pragma unroll
                for (int mf = 0; mf < 4; ++mf) {
                    mma_h(acc[mf][2*ng],   aH[mf], bF[ng][0], bF[ng][1]);
                    mma_h(acc[mf][2*ng+1], aH[mf], bF[ng][2], bF[ng][3]);
                }
            if (USE_LO) {
                #pragma unroll
                for (int ng = 0; ng < 2; ++ng)
                    #pragma unroll
                    for (int mf = 0; mf < 4; ++mf) {
                        mma_h(acc[mf][2*ng],   aL[mf], bF[ng][0], bF[ng][1]);
                        mma_h(acc[mf][2*ng+1], aL[mf], bF[ng][2], bF[ng][3]);
                    }
            }
        }
        __syncthreads();
    }
}

// ---------------- persistent QKV projection: grid 256, each CTA does z=0..2 -
__global__ void __launch_bounds__(256, 2) qkv_kernel(
    const float* __restrict__ bq, const float* __restrict__ bk, const float* __restrict__ bv)
{
    const int bid = blockIdx.x;
    const int n0 = (bid & 7) << 7;
    const int m0 = (bid >> 3) << 7;
    const int lane = threadIdx.x & 31, wid = threadIdx.x >> 5;
    const int wm = wid & 1, wn = wid >> 1;

    #pragma unroll 1
    for (int z = 0; z < 3; ++z) {
        const __half* Wh; const float* bias;
        __half *dh, *dl; float alpha; int dual;
        if (z == 0)      { Wh = g_Wq; bias = bq; dh = g_Qh; dl = g_Ql; alpha = 0.18033688011112042f; dual = 1; }
        else if (z == 1) { Wh = g_Wk; bias = bk; dh = g_Kh; dl = 0;    alpha = 1.0f; dual = 0; }
        else             { Wh = g_Wv; bias = bv; dh = g_Vh; dl = 0;    alpha = 1.0f; dual = 0; }

        float acc[4][4][4] = {};
        if (dual) gemm_body_128<true >(g_Xhi, g_Xlo, Wh, m0, n0, acc);
        else      gemm_body_128<false>(g_Xhi, g_Xlo, Wh, m0, n0, acc);

        #pragma unroll
        for (int mf = 0; mf < 4; ++mf)
            #pragma unroll
            for (int hh = 0; hh < 2; ++hh) {
                int m = m0 + wm*64 + mf*16 + hh*8 + (lane >> 2);
                int b = m >> 11, s = m & (SEQ-1);
                #pragma unroll
                for (int nf = 0; nf < 4; ++nf) {
                    int n = n0 + wn*32 + nf*8 + (lane & 3)*2;
                    int h = n >> 6, d = n & 63;
                    float v0 = (acc[mf][nf][hh*2+0] + bias[n])   * alpha;
                    float v1 = (acc[mf][nf][hh*2+1] + bias[n+1]) * alpha;
                    size_t o = ((size_t)(b*NH + h)*SEQ + s)*HD + d;
                    if (dual) {
                        uint32_t hp, lp; split2h(v0, v1, hp, lp);
                        *(uint32_t*)(dh + o) = hp;
                        *(uint32_t*)(dl + o) = lp;
                    } else {
                        *(uint32_t*)(dh + o) = packh(v0, v1);
                    }
                }
            }
    }
}

// ---------------- output projection (A single-term), grid 256 ---------------
__global__ void __launch_bounds__(256, 2) outproj_kernel(
    const float* __restrict__ bo, float* __restrict__ out)
{
    const int m0 = blockIdx.y << 7, n0 = blockIdx.x << 7;
    float acc[4][4][4] = {};
    gemm_body_128<false>(g_A, g_A, g_Wo, m0, n0, acc);

    const int lane = threadIdx.x & 31, wid = threadIdx.x >> 5;
    const int wm = wid & 1, wn = wid >> 1;
    #pragma unroll
    for (int mf = 0; mf < 4; ++mf)
        #pragma unroll
        for (int hh = 0; hh < 2; ++hh) {
            int m = m0 + wm*64 + mf*16 + hh*8 + (lane >> 2);
            #pragma unroll
            for (int nf = 0; nf < 4; ++nf) {
                int n = n0 + wn*32 + nf*8 + (lane & 3)*2;
                float2 v = make_float2(acc[mf][nf][hh*2+0] + bo[n],
                                       acc[mf][nf][hh*2+1] + bo[n+1]);
                *(float2*)&out[(size_t)m * EMB + n] = v;
            }
        }
}

// ---------------- persistent flash attention: grid 256, 2 Q-tiles per CTA ---
#define ASP     144
#define QL_OFF  18432
#define KV_BASE 36864
#define V_OFF   9216
#define KV_STG  18432
#define ATT_SMEM (KV_BASE + 3*KV_STG)   // 92160

__global__ void __launch_bounds__(256, 2) attn_kernel()
{
    extern __shared__ char sm[];
    const uint32_t smb = smem_u32(sm);
    const int tid = threadIdx.x, lane = tid & 31, w = tid >> 5;

    #pragma unroll 1
    for (int rep = 0; rep < 2; ++rep) {
        const int t = blockIdx.x + (rep << 8);
        const int bh = t >> 4;
        const int q0 = (t & 15) << 7;

        const __half* Qh = g_Qh + ((size_t)bh*SEQ + q0)*HD;
        const __half* Ql = g_Ql + ((size_t)bh*SEQ + q0)*HD;
        const __half* Kh = g_Kh + (size_t)bh*SEQ*HD;
        const __half* Vh = g_Vh + (size_t)bh*SEQ*HD;

        auto issue_kv = [&](int it) {
            const int kv0 = it << 6;
            const uint32_t sb = smb + KV_BASE + (uint32_t)(it % 3) * KV_STG;
            #pragma unroll
            for (int j = 0; j < 4; ++j) {
                int idx = tid + (j << 8);
                int arr = idx >> 9, c = idx & 511;
                int row = c >> 3, seg = c & 7;
                size_t ga = (size_t)(kv0 + row)*HD + seg*8;
                const __half* g = (arr == 0) ? Kh : Vh;
                cp16(sb + arr*V_OFF + row*ASP + seg*16, g + ga);
            }
            CP_COMMIT();
        };

        __syncthreads();   // protect smem reuse across reps
        // Q: 128 rows x 8 segs x {hi,lo} = 2048 chunks -> 8 per thread
        #pragma unroll
        for (int j = 0; j < 8; ++j) {
            int idx = tid + (j << 8);
            int lo_ = idx >> 10, c = idx & 1023;
            int row = c >> 3, seg = c & 7;
            const __half* g = (lo_ ? Ql : Qh) + (size_t)row*HD + seg*8;
            cp16(smb + (lo_ ? QL_OFF : 0) + row*ASP + seg*16, g);
        }
        CP_COMMIT();
        issue_kv(0);
        issue_kv(1);

        float o[8][4] = {};
        float m0_ = __int_as_float(0xff800000), m1_ = m0_;
        float l0_ = 0.f, l1_ = 0.f;

        for (int it = 0; it < SEQ/64; ++it) {
            if (it + 1 < SEQ/64) CP_WAIT(1); else CP_WAIT(0);
            __syncthreads();
            if (it + 2 < SEQ/64) issue_kv(it + 2);
            const uint32_t kb = smb + KV_BASE + (uint32_t)(it % 3) * KV_STG;

            // S = Q K^T (Q 2-term)
            float s[8][4] = {};
            #pragma unroll
            for (int ks = 0; ks < 4; ++ks) {
                uint32_t aQh[4], aQl[4], bF[4][4];
                uint32_t qrow = w*16 + ((lane>>3)&1)*8 + (lane&7);
                uint32_t qcol = ks*32 + ((lane>>4)&1)*16;
                ldsm4(aQh, smb + qrow*ASP + qcol);
                ldsm4(aQl, smb + QL_OFF + qrow*ASP + qcol);
                #pragma unroll
                for (int ng = 0; ng < 4; ++ng) {
                    uint32_t krow = ng*16 + ((lane>>4)&1)*8 + (lane&7);
                    uint32_t kcol = ks*32 + ((lane>>3)&1)*16;
                    ldsm4(bF[ng], kb + krow*ASP + kcol);
                }
                #pragma unroll
                for (int ng = 0; ng < 4; ++ng) {
                    mma_h(s[2*ng],   aQh, bF[ng][0], bF[ng][1]);
                    mma_h(s[2*ng+1], aQh, bF[ng][2], bF[ng][3]);
                }
                #pragma unroll
                for (int ng = 0; ng < 4; ++ng) {
                    mma_h(s[2*ng],   aQl, bF[ng][0], bF[ng][1]);
                    mma_h(s[2*ng+1], aQl, bF[ng][2], bF[ng][3]);
                }
            }

            // online softmax (rows lane>>2 and +8); sums via ones-MMA
            float mx0 = fmaxf(s[0][0], s[0][1]), mx1 = fmaxf(s[0][2], s[0][3]);
            #pragma unroll
            for (int j = 1; j < 8; ++j) {
                mx0 = fmaxf(mx0, fmaxf(s[j][0], s[j][1]));
                mx1 = fmaxf(mx1, fmaxf(s[j][2], s[j][3]));
            }
            mx0 = fmaxf(mx0, __shfl_xor_sync(0xffffffffu, mx0, 1));
            mx0 = fmaxf(mx0, __shfl_xor_sync(0xffffffffu, mx0, 2));
            mx1 = fmaxf(mx1, __shfl_xor_sync(0xffffffffu, mx1, 1));
            mx1 = fmaxf(mx1, __shfl_xor_sync(0xffffffffu, mx1, 2));
            float mn0 = fmaxf(m0_, mx0), mn1 = fmaxf(m1_, mx1);
            float c0 = exp2f(m0_ - mn0), c1 = exp2f(m1_ - mn1);
            m0_ = mn0; m1_ = mn1;
            #pragma unroll
            for (int j = 0; j < 8; ++j) {
                o[j][0] *= c0; o[j][1] *= c0; o[j][2] *= c1; o[j][3] *= c1;
            }

            // O += P V ; l += P @ ones.  P = ex2(s - mn) in fp16x2 directly.
            float lacc[4] = {};
            #pragma unroll
            for (int ks = 0; ks < 4; ++ks) {
                uint32_t aP[4];
                aP[0] = ex2h2(packh(s[2*ks][0]   - mn0, s[2*ks][1]   - mn0));
                aP[1] = ex2h2(packh(s[2*ks][2]   - mn1, s[2*ks][3]   - mn1));
                aP[2] = ex2h2(packh(s[2*ks+1][0] - mn0, s[2*ks+1][1] - mn0));
                aP[3] = ex2h2(packh(s[2*ks+1][2] - mn1, s[2*ks+1][3] - mn1));
                mma_h(lacc, aP, ONESH2, ONESH2);
                #pragma unroll
                for (int ng = 0; ng < 4; ++ng) {
                    uint32_t bH[4];
                    uint32_t vrow = ks*16 + ((lane>>3)&1)*8 + (lane&7);
                    uint32_t vcol = ng*32 + ((lane>>4)&1)*16;
                    ldsm4t(bH, kb + V_OFF + vrow*ASP + vcol);
                    mma_h(o[2*ng],   aP, bH[0], bH[1]);
                    mma_h(o[2*ng+1], aP, bH[2], bH[3]);
                }
            }
            l0_ = l0_ * c0 + lacc[0];
            l1_ = l1_ * c1 + lacc[2];
        }

        // epilogue -> single fp16 A in [B*S][EMB]
        const int b = bh >> 4, h = bh & 15;
        float inv0 = 1.0f / l0_, inv1 = 1.0f / l1_;
        const int r0 = q0 + w*16 + (lane >> 2), r1 = r0 + 8;
        #pragma unroll
        for (int nf = 0; nf < 8; ++nf) {
            int d = nf*8 + (lane & 3)*2;
            int e = h*HD + d;
            *(uint32_t*)(g_A + ((size_t)(b*SEQ + r0))*EMB + e) = packh(o[nf][0]*inv0, o[nf][1]*inv0);
            *(uint32_t*)(g_A + ((size_t)(b*SEQ + r1))*EMB + e) = packh(o[nf][2]*inv1, o[nf][3]*inv1);
        }
    }
}

// ---------------------------------------------------------------------------
extern "C" void kernel_launch(void* const* d_in, const int* in_sizes, int n_in,
                              void* d_out, int out_size)
{
    (void)in_sizes; (void)n_in; (void)out_size;
    const float* x  = (const float*)d_in[0];
    const float* Wq = (const float*)d_in[1];
    const float* bq = (const float*)d_in[2];
    const float* Wk = (const float*)d_in[3];
    const float* bk = (const float*)d_in[4];
    const float* Wv = (const float*)d_in[5];
    const float* bv = (const float*)d_in[6];
    const float* Wo = (const float*)d_in[7];
    const float* bo = (const float*)d_in[8];
    float* out = (float*)d_out;

    cudaFuncSetAttribute(qkv_kernel,     cudaFuncAttributeMaxDynamicSharedMemorySize, GEMM_SMEM);
    cudaFuncSetAttribute(outproj_kernel, cudaFuncAttributeMaxDynamicSharedMemorySize, GEMM_SMEM);
    cudaFuncSetAttribute(attn_kernel,    cudaFuncAttributeMaxDynamicSharedMemorySize, ATT_SMEM);

    split_all_kernel<<<4096, 256>>>(x, Wq, Wk, Wv, Wo);

    qkv_kernel<<<256, 256, GEMM_SMEM>>>(bq, bk, bv);   // persistent over z

    attn_kernel<<<256, 256, ATT_SMEM>>>();             // persistent, 2 Q-tiles/CTA

    dim3 gout(EMB/128, MTOK/128);                      // 8 x 32 = 256
    outproj_kernel<<<gout, 256, GEMM_SMEM>>>(bo, out);
}

// round 14
// speedup vs baseline: 1.1938x; 1.1938x over previous
#include <cuda_runtime.h>
#include <cuda_fp16.h>
#include <cstdint>

#define EMB   1024
#define NH    16
#define HD    64
#define BATCH 2
#define SEQ   2048
#define MTOK  (BATCH*SEQ)   // 4096
#define BHN   (BATCH*NH)    // 32

// ---------------- scratch (__device__ globals; no allocs allowed) -----------
__device__ __half g_Xh[(size_t)MTOK*EMB];
__device__ __half g_A[(size_t)MTOK*EMB];
__device__ __half g_Qh[(size_t)MTOK*EMB];
__device__ __half g_Kh[(size_t)MTOK*EMB];
__device__ __half g_Vh[(size_t)MTOK*EMB];
__device__ __half g_Wq[(size_t)EMB*EMB], g_Wk[(size_t)EMB*EMB];
__device__ __half g_Wv[(size_t)EMB*EMB], g_Wo[(size_t)EMB*EMB];

// ---------------- helpers ---------------------------------------------------
__device__ __forceinline__ uint32_t smem_u32(const void* p) {
    uint32_t a;
    asm("{ .reg .u64 t; cvta.to.shared.u64 t, %1; cvt.u32.u64 %0, t; }" : "=r"(a) : "l"(p));
    return a;
}
__device__ __forceinline__ void cp16(uint32_t d, const void* s) {
    asm volatile("cp.async.cg.shared.global [%0], [%1], 16;" :: "r"(d), "l"(s));
}
#define CP_COMMIT() asm volatile("cp.async.commit_group;")
#define CP_WAIT(n)  asm volatile("cp.async.wait_group %0;" :: "n"(n))

__device__ __forceinline__ void ldsm4(uint32_t (&r)[4], uint32_t a) {
    asm volatile("ldmatrix.sync.aligned.m8n8.x4.shared.b16 {%0,%1,%2,%3}, [%4];"
        : "=r"(r[0]), "=r"(r[1]), "=r"(r[2]), "=r"(r[3]) : "r"(a));
}
__device__ __forceinline__ void ldsm4t(uint32_t (&r)[4], uint32_t a) {
    asm volatile("ldmatrix.sync.aligned.m8n8.x4.trans.shared.b16 {%0,%1,%2,%3}, [%4];"
        : "=r"(r[0]), "=r"(r[1]), "=r"(r[2]), "=r"(r[3]) : "r"(a));
}
__device__ __forceinline__ void mma_h(float (&c)[4], const uint32_t (&a)[4], uint32_t b0, uint32_t b1) {
    asm("mma.sync.aligned.m16n8k16.row.col.f32.f16.f16.f32 "
        "{%0,%1,%2,%3}, {%4,%5,%6,%7}, {%8,%9}, {%0,%1,%2,%3};"
        : "+f"(c[0]), "+f"(c[1]), "+f"(c[2]), "+f"(c[3])
        : "r"(a[0]), "r"(a[1]), "r"(a[2]), "r"(a[3]), "r"(b0), "r"(b1));
}
__device__ __forceinline__ uint32_t packh(float v0, float v1) {
    __half2 h = __floats2half2_rn(v0, v1);
    return *(uint32_t*)&h;
}
__device__ __forceinline__ uint32_t ex2h2(uint32_t x) {
    uint32_t r;
    asm("ex2.approx.f16x2 %0, %1;" : "=r"(r) : "r"(x));
    return r;
}
#define ONESH2 0x3C003C00u   // half2(1.0, 1.0)

// ---------------- fused fp32 -> fp16 pack (all 5 tensors, single-term) ------
__global__ __launch_bounds__(256) void split_all_kernel(
    const float* __restrict__ x,  const float* __restrict__ wq,
    const float* __restrict__ wk, const float* __restrict__ wv,
    const float* __restrict__ wo)
{
    int i = blockIdx.x * 256 + threadIdx.x;
    const float* src; __half* dst; int off;
    if (i < 524288) { src = x; dst = g_Xh; off = i; }
    else {
        int j = i - 524288;
        int w = j >> 17;
        off = j & 131071;
        if (w == 0)      { src = wq; dst = g_Wq; }
        else if (w == 1) { src = wk; dst = g_Wk; }
        else if (w == 2) { src = wv; dst = g_Wv; }
        else             { src = wo; dst = g_Wo; }
    }
    float4 a = ((const float4*)src)[2*off];
    float4 b = ((const float4*)src)[2*off + 1];
    uint32_t hp[4];
    hp[0] = packh(a.x, a.y); hp[1] = packh(a.z, a.w);
    hp[2] = packh(b.x, b.y); hp[3] = packh(b.z, b.w);
    ((uint4*)dst)[off] = make_uint4(hp[0], hp[1], hp[2], hp[3]);
}

// ---------------- GEMM body: 128x128 CTA, 8 warps 64x32, 2-stage, 2 CTA/SM --
#define SPAD   80
#define B_OFF  10240
#define STG    20480
#define GEMM_SMEM (2*STG)   // 40960
#define NITER (EMB/32)      // 32

__device__ __forceinline__ void gemm_body_128(
    const __half* __restrict__ Ah, const __half* __restrict__ Wh,
    int m0, int n0, float (&acc)[4][4][4])
{
    extern __shared__ char sm[];
    const uint32_t smb = smem_u32(sm);
    const int tid = threadIdx.x, lane = tid & 31, wid = tid >> 5;
    const int wm = wid & 1, wn = wid >> 1;   // 2 x 4 warp grid, warp tile 64x32

    auto issue = [&](int it) {
        const int k0 = it << 5;
        const uint32_t sb = smb + (uint32_t)(it & 1) * STG;
        // 1024 chunks: A 512 | B 512 -> 4 per thread
        #pragma unroll
        for (int j = 0; j < 4; ++j) {
            int idx = tid + (j << 8);
            if (idx < 512) {
                int row = idx >> 2, seg = idx & 3;
                cp16(sb + row*SPAD + seg*16, Ah + (size_t)(m0 + row)*EMB + k0 + seg*8);
            } else {
                int c = idx - 512, row = c >> 2, seg = c & 3;
                cp16(sb + B_OFF + row*SPAD + seg*16, Wh + (size_t)(n0 + row)*EMB + k0 + seg*8);
            }
        }
        CP_COMMIT();
    };

    issue(0);
    for (int it = 0; it < NITER; ++it) {
        CP_WAIT(0);
        __syncthreads();
        if (it + 1 < NITER) issue(it + 1);
        const uint32_t sb = smb + (uint32_t)(it & 1) * STG;
        #pragma unroll
        for (int ks = 0; ks < 2; ++ks) {
            uint32_t aH[4][4], bF[2][4];
            uint32_t acol = ks*32 + ((lane>>4)&1)*16;
            #pragma unroll
            for (int mf = 0; mf < 4; ++mf) {
                uint32_t row = wm*64 + mf*16 + ((lane>>3)&1)*8 + (lane&7);
                ldsm4(aH[mf], sb + row*SPAD + acol);
            }
            #pragma unroll
            for (int ng = 0; ng < 2; ++ng) {
                uint32_t row = wn*32 + ng*16 + ((lane>>4)&1)*8 + (lane&7);
                uint32_t col = ks*32 + ((lane>>3)&1)*16;
                ldsm4(bF[ng], sb + B_OFF + row*SPAD + col);
            }
            #pragma unroll
            for (int ng = 0; ng < 2; ++ng)
                #pragma unroll
                for (int mf = 0; mf < 4; ++mf) {
                    mma_h(acc[mf][2*ng],   aH[mf], bF[ng][0], bF[ng][1]);
                    mma_h(acc[mf][2*ng+1], aH[mf], bF[ng][2], bF[ng][3]);
                }
        }
        __syncthreads();
    }
}

// ---------------- QKV projection (all single-term) ---------------------------
__global__ void __launch_bounds__(256, 2) qkv_kernel(
    const float* __restrict__ bq, const float* __restrict__ bk, const float* __restrict__ bv)
{
    const __half* Wh; const float* bias; __half* dh; float alpha;
    if (blockIdx.z == 0)      { Wh = g_Wq; bias = bq; dh = g_Qh; alpha = 0.18033688011112042f; }
    else if (blockIdx.z == 1) { Wh = g_Wk; bias = bk; dh = g_Kh; alpha = 1.0f; }
    else                      { Wh = g_Wv; bias = bv; dh = g_Vh; alpha = 1.0f; }

    const int m0 = blockIdx.y << 7, n0 = blockIdx.x << 7;
    float acc[4][4][4] = {};
    gemm_body_128(g_Xh, Wh, m0, n0, acc);

    const int lane = threadIdx.x & 31, wid = threadIdx.x >> 5;
    const int wm = wid & 1, wn = wid >> 1;
    #pragma unroll
    for (int mf = 0; mf < 4; ++mf)
        #pragma unroll
        for (int hh = 0; hh < 2; ++hh) {
            int m = m0 + wm*64 + mf*16 + hh*8 + (lane >> 2);
            int b = m >> 11, s = m & (SEQ-1);
            #pragma unroll
            for (int nf = 0; nf < 4; ++nf) {
                int n = n0 + wn*32 + nf*8 + (lane & 3)*2;
                int h = n >> 6, d = n & 63;
                float v0 = (acc[mf][nf][hh*2+0] + bias[n])   * alpha;
                float v1 = (acc[mf][nf][hh*2+1] + bias[n+1]) * alpha;
                size_t o = ((size_t)(b*NH + h)*SEQ + s)*HD + d;
                *(uint32_t*)(dh + o) = packh(v0, v1);
            }
        }
}

// ---------------- output projection (A single-term) --------------------------
__global__ void __launch_bounds__(256, 2) outproj_kernel(
    const float* __restrict__ bo, float* __restrict__ out)
{
    const int m0 = blockIdx.y << 7, n0 = blockIdx.x << 7;
    float acc[4][4][4] = {};
    gemm_body_128(g_A, g_Wo, m0, n0, acc);

    const int lane = threadIdx.x & 31, wid = threadIdx.x >> 5;
    const int wm = wid & 1, wn = wid >> 1;
    #pragma unroll
    for (int mf = 0; mf < 4; ++mf)
        #pragma unroll
        for (int hh = 0; hh < 2; ++hh) {
            int m = m0 + wm*64 + mf*16 + hh*8 + (lane >> 2);
            #pragma unroll
            for (int nf = 0; nf < 4; ++nf) {
                int n = n0 + wn*32 + nf*8 + (lane & 3)*2;
                float2 v = make_float2(acc[mf][nf][hh*2+0] + bo[n],
                                       acc[mf][nf][hh*2+1] + bo[n+1]);
                *(float2*)&out[(size_t)m * EMB + n] = v;
            }
        }
}

// ---------------- flash attention: BQ=128, 8 warps m16, 3-stage, 2 CTA/SM ---
// Q single fp16, K single, P single via ex2.f16x2, V single. Sums via ones-MMA.
#define ASP     144
#define KV_BASE 18432
#define V_OFF   9216
#define KV_STG  18432
#define ATT_SMEM (KV_BASE + 3*KV_STG)   // 73728

__global__ void __launch_bounds__(256, 2) attn_kernel()
{
    extern __shared__ char sm[];
    const uint32_t smb = smem_u32(sm);
    const int tid = threadIdx.x, lane = tid & 31, w = tid >> 5;
    const int bh = blockIdx.y, q0 = blockIdx.x << 7;

    const __half* Qh = g_Qh + ((size_t)bh*SEQ + q0)*HD;
    const __half* Kh = g_Kh + (size_t)bh*SEQ*HD;
    const __half* Vh = g_Vh + (size_t)bh*SEQ*HD;

    auto issue_kv = [&](int it) {
        const int kv0 = it << 6;
        const uint32_t sb = smb + KV_BASE + (uint32_t)(it % 3) * KV_STG;
        #pragma unroll
        for (int j = 0; j < 4; ++j) {
            int idx = tid + (j << 8);
            int arr = idx >> 9, c = idx & 511;
            int row = c >> 3, seg = c & 7;
            size_t ga = (size_t)(kv0 + row)*HD + seg*8;
            const __half* g = (arr == 0) ? Kh : Vh;
            cp16(sb + arr*V_OFF + row*ASP + seg*16, g + ga);
        }
        CP_COMMIT();
    };

    // Q: 128 rows x 8 segs = 1024 chunks -> 4 per thread
    #pragma unroll
    for (int j = 0; j < 4; ++j) {
        int idx = tid + (j << 8);
        int row = idx >> 3, seg = idx & 7;
        cp16(smb + row*ASP + seg*16, Qh + (size_t)row*HD + seg*8);
    }
    CP_COMMIT();
    issue_kv(0);
    issue_kv(1);

    float o[8][4] = {};
    float m0_ = __int_as_float(0xff800000), m1_ = m0_;
    float l0_ = 0.f, l1_ = 0.f;

    for (int it = 0; it < SEQ/64; ++it) {
        if (it + 1 < SEQ/64) CP_WAIT(1); else CP_WAIT(0);
        __syncthreads();
        if (it + 2 < SEQ/64) issue_kv(it + 2);
        const uint32_t kb = smb + KV_BASE + (uint32_t)(it % 3) * KV_STG;

        // S = Q K^T (both single fp16)
        float s[8][4] = {};
        #pragma unroll
        for (int ks = 0; ks < 4; ++ks) {
            uint32_t aQ[4], bF[4][4];
            uint32_t qrow = w*16 + ((lane>>3)&1)*8 + (lane&7);
            uint32_t qcol = ks*32 + ((lane>>4)&1)*16;
            ldsm4(aQ, smb + qrow*ASP + qcol);
            #pragma unroll
            for (int ng = 0; ng < 4; ++ng) {
                uint32_t krow = ng*16 + ((lane>>4)&1)*8 + (lane&7);
                uint32_t kcol = ks*32 + ((lane>>3)&1)*16;
                ldsm4(bF[ng], kb + krow*ASP + kcol);
            }
            #pragma unroll
            for (int ng = 0; ng < 4; ++ng) {
                mma_h(s[2*ng],   aQ, bF[ng][0], bF[ng][1]);
                mma_h(s[2*ng+1], aQ, bF[ng][2], bF[ng][3]);
            }
        }

        // online softmax (rows lane>>2 and +8); sums via ones-MMA
        float mx0 = fmaxf(s[0][0], s[0][1]), mx1 = fmaxf(s[0][2], s[0][3]);
        #pragma unroll
        for (int j = 1; j < 8; ++j) {
            mx0 = fmaxf(mx0, fmaxf(s[j][0], s[j][1]));
            mx1 = fmaxf(mx1, fmaxf(s[j][2], s[j][3]));
        }
        mx0 = fmaxf(mx0, __shfl_xor_sync(0xffffffffu, mx0, 1));
        mx0 = fmaxf(mx0, __shfl_xor_sync(0xffffffffu, mx0, 2));
        mx1 = fmaxf(mx1, __shfl_xor_sync(0xffffffffu, mx1, 1));
        mx1 = fmaxf(mx1, __shfl_xor_sync(0xffffffffu, mx1, 2));
        float mn0 = fmaxf(m0_, mx0), mn1 = fmaxf(m1_, mx1);
        float c0 = exp2f(m0_ - mn0), c1 = exp2f(m1_ - mn1);
        m0_ = mn0; m1_ = mn1;
        #pragma unroll
        for (int j = 0; j < 8; ++j) {
            o[j][0] *= c0; o[j][1] *= c0; o[j][2] *= c1; o[j][3] *= c1;
        }

        // O += P V ; l += P @ ones.  P = ex2(s - mn) in fp16x2 directly.
        float lacc[4] = {};
        #pragma unroll
        for (int ks = 0; ks < 4; ++ks) {
            uint32_t aP[4];
            aP[0] = ex2h2(packh(s[2*ks][0]   - mn0, s[2*ks][1]   - mn0));
            aP[1] = ex2h2(packh(s[2*ks][2]   - mn1, s[2*ks][3]   - mn1));
            aP[2] = ex2h2(packh(s[2*ks+1][0] - mn0, s[2*ks+1][1] - mn0));
            aP[3] = ex2h2(packh(s[2*ks+1][2] - mn1, s[2*ks+1][3] - mn1));
            mma_h(lacc, aP, ONESH2, ONESH2);
            #pragma unroll
            for (int ng = 0; ng < 4; ++ng) {
                uint32_t bH[4];
                uint32_t vrow = ks*16 + ((lane>>3)&1)*8 + (lane&7);
                uint32_t vcol = ng*32 + ((lane>>4)&1)*16;
                ldsm4t(bH, kb + V_OFF + vrow*ASP + vcol);
                mma_h(o[2*ng],   aP, bH[0], bH[1]);
                mma_h(o[2*ng+1], aP, bH[2], bH[3]);
            }
        }
        l0_ = l0_ * c0 + lacc[0];
        l1_ = l1_ * c1 + lacc[2];
    }

    // epilogue -> single fp16 A in [B*S][EMB]
    const int b = bh >> 4, h = bh & 15;
    float inv0 = 1.0f / l0_, inv1 = 1.0f / l1_;
    const int r0 = q0 + w*16 + (lane >> 2), r1 = r0 + 8;
    #pragma unroll
    for (int nf = 0; nf < 8; ++nf) {
        int d = nf*8 + (lane & 3)*2;
        int e = h*HD + d;
        *(uint32_t*)(g_A + ((size_t)(b*SEQ + r0))*EMB + e) = packh(o[nf][0]*inv0, o[nf][1]*inv0);
        *(uint32_t*)(g_A + ((size_t)(b*SEQ + r1))*EMB + e) = packh(o[nf][2]*inv1, o[nf][3]*inv1);
    }
}

// ---------------------------------------------------------------------------
extern "C" void kernel_launch(void* const* d_in, const int* in_sizes, int n_in,
                              void* d_out, int out_size)
{
    (void)in_sizes; (void)n_in; (void)out_size;
    const float* x  = (const float*)d_in[0];
    const float* Wq = (const float*)d_in[1];
    const float* bq = (const float*)d_in[2];
    const float* Wk = (const float*)d_in[3];
    const float* bk = (const float*)d_in[4];
    const float* Wv = (const float*)d_in[5];
    const float* bv = (const float*)d_in[6];
    const float* Wo = (const float*)d_in[7];
    const float* bo = (const float*)d_in[8];
    float* out = (float*)d_out;

    cudaFuncSetAttribute(qkv_kernel,     cudaFuncAttributeMaxDynamicSharedMemorySize, GEMM_SMEM);
    cudaFuncSetAttribute(outproj_kernel, cudaFuncAttributeMaxDynamicSharedMemorySize, GEMM_SMEM);
    cudaFuncSetAttribute(attn_kernel,    cudaFuncAttributeMaxDynamicSharedMemorySize, ATT_SMEM);

    split_all_kernel<<<4096, 256>>>(x, Wq, Wk, Wv, Wo);

    dim3 gqkv(EMB/128, MTOK/128, 3);     // 8 x 32 x 3 = 768 CTAs (dynamic balance)
    qkv_kernel<<<gqkv, 256, GEMM_SMEM>>>(bq, bk, bv);

    dim3 gattn(SEQ/128, BHN);            // 16 x 32 = 512 CTAs
    attn_kernel<<<gattn, 256, ATT_SMEM>>>();

    dim3 gout(EMB/128, MTOK/128);        // 8 x 32 = 256
    outproj_kernel<<<gout, 256, GEMM_SMEM>>>(bo, out);
}

// round 15
// speedup vs baseline: 1.2561x; 1.0522x over previous
#include <cuda_runtime.h>
#include <cuda_fp16.h>
#include <cstdint>

#define EMB   1024
#define NH    16
#define HD    64
#define BATCH 2
#define SEQ   2048
#define MTOK  (BATCH*SEQ)   // 4096
#define BHN   (BATCH*NH)    // 32

// ---------------- scratch (__device__ globals; no allocs allowed) -----------
__device__ __half g_Xh[(size_t)MTOK*EMB];
__device__ __half g_A[(size_t)MTOK*EMB];
__device__ __half g_Qh[(size_t)MTOK*EMB];
__device__ __half g_Kh[(size_t)MTOK*EMB];
__device__ __half g_Vh[(size_t)MTOK*EMB];
__device__ __half g_Wq[(size_t)EMB*EMB], g_Wk[(size_t)EMB*EMB];
__device__ __half g_Wv[(size_t)EMB*EMB], g_Wo[(size_t)EMB*EMB];

// ---------------- helpers ---------------------------------------------------
__device__ __forceinline__ uint32_t smem_u32(const void* p) {
    uint32_t a;
    asm("{ .reg .u64 t; cvta.to.shared.u64 t, %1; cvt.u32.u64 %0, t; }" : "=r"(a) : "l"(p));
    return a;
}
__device__ __forceinline__ void cp16(uint32_t d, const void* s) {
    asm volatile("cp.async.cg.shared.global [%0], [%1], 16;" :: "r"(d), "l"(s));
}
#define CP_COMMIT() asm volatile("cp.async.commit_group;")
#define CP_WAIT(n)  asm volatile("cp.async.wait_group %0;" :: "n"(n))

__device__ __forceinline__ void ldsm4(uint32_t (&r)[4], uint32_t a) {
    asm volatile("ldmatrix.sync.aligned.m8n8.x4.shared.b16 {%0,%1,%2,%3}, [%4];"
        : "=r"(r[0]), "=r"(r[1]), "=r"(r[2]), "=r"(r[3]) : "r"(a));
}
__device__ __forceinline__ void ldsm4t(uint32_t (&r)[4], uint32_t a) {
    asm volatile("ldmatrix.sync.aligned.m8n8.x4.trans.shared.b16 {%0,%1,%2,%3}, [%4];"
        : "=r"(r[0]), "=r"(r[1]), "=r"(r[2]), "=r"(r[3]) : "r"(a));
}
__device__ __forceinline__ void mma_h(float (&c)[4], const uint32_t (&a)[4], uint32_t b0, uint32_t b1) {
    asm("mma.sync.aligned.m16n8k16.row.col.f32.f16.f16.f32 "
        "{%0,%1,%2,%3}, {%4,%5,%6,%7}, {%8,%9}, {%0,%1,%2,%3};"
        : "+f"(c[0]), "+f"(c[1]), "+f"(c[2]), "+f"(c[3])
        : "r"(a[0]), "r"(a[1]), "r"(a[2]), "r"(a[3]), "r"(b0), "r"(b1));
}
__device__ __forceinline__ uint32_t packh(float v0, float v1) {
    __half2 h = __floats2half2_rn(v0, v1);
    return *(uint32_t*)&h;
}
__device__ __forceinline__ uint32_t ex2h2(uint32_t x) {
    uint32_t r;
    asm("ex2.approx.f16x2 %0, %1;" : "=r"(r) : "r"(x));
    return r;
}
#define ONESH2 0x3C003C00u   // half2(1.0, 1.0)

// ---------------- fused fp32 -> fp16 pack (all 5 tensors) --------------------
__global__ __launch_bounds__(256) void split_all_kernel(
    const float* __restrict__ x,  const float* __restrict__ wq,
    const float* __restrict__ wk, const float* __restrict__ wv,
    const float* __restrict__ wo)
{
    int i = blockIdx.x * 256 + threadIdx.x;
    const float* src; __half* dst; int off;
    if (i < 524288) { src = x; dst = g_Xh; off = i; }
    else {
        int j = i - 524288;
        int w = j >> 17;
        off = j & 131071;
        if (w == 0)      { src = wq; dst = g_Wq; }
        else if (w == 1) { src = wk; dst = g_Wk; }
        else if (w == 2) { src = wv; dst = g_Wv; }
        else             { src = wo; dst = g_Wo; }
    }
    float4 a = ((const float4*)src)[2*off];
    float4 b = ((const float4*)src)[2*off + 1];
    uint32_t hp[4];
    hp[0] = packh(a.x, a.y); hp[1] = packh(a.z, a.w);
    hp[2] = packh(b.x, b.y); hp[3] = packh(b.z, b.w);
    ((uint4*)dst)[off] = make_uint4(hp[0], hp[1], hp[2], hp[3]);
}

// ---------------- GEMM body: 128x128 CTA, BK=64, 2-stage, 2 CTA/SM ----------
#define SPAD   144
#define B_OFF  18432
#define STG    36864
#define GEMM_SMEM (2*STG)   // 73728
#define NITER (EMB/64)      // 16

__device__ __forceinline__ void gemm_body_128(
    const __half* __restrict__ Ah, const __half* __restrict__ Wh,
    int m0, int n0, float (&acc)[4][4][4])
{
    extern __shared__ char sm[];
    const uint32_t smb = smem_u32(sm);
    const int tid = threadIdx.x, lane = tid & 31, wid = tid >> 5;
    const int wm = wid & 1, wn = wid >> 1;   // 2 x 4 warp grid, warp tile 64x32

    auto issue = [&](int it) {
        const int k0 = it << 6;
        const uint32_t sb = smb + (uint32_t)(it & 1) * STG;
        // 2048 chunks: A 1024 | B 1024 -> 8 per thread
        #pragma unroll
        for (int j = 0; j < 8; ++j) {
            int idx = tid + (j << 8);
            if (idx < 1024) {
                int row = idx >> 3, seg = idx & 7;
                cp16(sb + row*SPAD + seg*16, Ah + (size_t)(m0 + row)*EMB + k0 + seg*8);
            } else {
                int c = idx - 1024, row = c >> 3, seg = c & 7;
                cp16(sb + B_OFF + row*SPAD + seg*16, Wh + (size_t)(n0 + row)*EMB + k0 + seg*8);
            }
        }
        CP_COMMIT();
    };

    issue(0);
    for (int it = 0; it < NITER; ++it) {
        CP_WAIT(0);
        __syncthreads();
        if (it + 1 < NITER) issue(it + 1);
        const uint32_t sb = smb + (uint32_t)(it & 1) * STG;
        #pragma unroll
        for (int ks = 0; ks < 4; ++ks) {
            uint32_t aH[4][4], bF[2][4];
            uint32_t acol = ks*32 + ((lane>>4)&1)*16;
            #pragma unroll
            for (int mf = 0; mf < 4; ++mf) {
                uint32_t row = wm*64 + mf*16 + ((lane>>3)&1)*8 + (lane&7);
                ldsm4(aH[mf], sb + row*SPAD + acol);
            }
            #pragma unroll
            for (int ng = 0; ng < 2; ++ng) {
                uint32_t row = wn*32 + ng*16 + ((lane>>4)&1)*8 + (lane&7);
                uint32_t col = ks*32 + ((lane>>3)&1)*16;
                ldsm4(bF[ng], sb + B_OFF + row*SPAD + col);
            }
            #pragma unroll
            for (int ng = 0; ng < 2; ++ng)
                #pragma unroll
                for (int mf = 0; mf < 4; ++mf) {
                    mma_h(acc[mf][2*ng],   aH[mf], bF[ng][0], bF[ng][1]);
                    mma_h(acc[mf][2*ng+1], aH[mf], bF[ng][2], bF[ng][3]);
                }
        }
        __syncthreads();
    }
}

// ---------------- QKV projection (all single-term) ---------------------------
__global__ void __launch_bounds__(256, 2) qkv_kernel(
    const float* __restrict__ bq, const float* __restrict__ bk, const float* __restrict__ bv)
{
    const __half* Wh; const float* bias; __half* dh; float alpha;
    if (blockIdx.z == 0)      { Wh = g_Wq; bias = bq; dh = g_Qh; alpha = 0.18033688011112042f; }
    else if (blockIdx.z == 1) { Wh = g_Wk; bias = bk; dh = g_Kh; alpha = 1.0f; }
    else                      { Wh = g_Wv; bias = bv; dh = g_Vh; alpha = 1.0f; }

    const int m0 = blockIdx.y << 7, n0 = blockIdx.x << 7;
    float acc[4][4][4] = {};
    gemm_body_128(g_Xh, Wh, m0, n0, acc);

    const int lane = threadIdx.x & 31, wid = threadIdx.x >> 5;
    const int wm = wid & 1, wn = wid >> 1;
    #pragma unroll
    for (int mf = 0; mf < 4; ++mf)
        #pragma unroll
        for (int hh = 0; hh < 2; ++hh) {
            int m = m0 + wm*64 + mf*16 + hh*8 + (lane >> 2);
            int b = m >> 11, s = m & (SEQ-1);
            #pragma unroll
            for (int nf = 0; nf < 4; ++nf) {
                int n = n0 + wn*32 + nf*8 + (lane & 3)*2;
                int h = n >> 6, d = n & 63;
                float v0 = (acc[mf][nf][hh*2+0] + bias[n])   * alpha;
                float v1 = (acc[mf][nf][hh*2+1] + bias[n+1]) * alpha;
                size_t o = ((size_t)(b*NH + h)*SEQ + s)*HD + d;
                *(uint32_t*)(dh + o) = packh(v0, v1);
            }
        }
}

// ---------------- output projection -----------------------------------------
__global__ void __launch_bounds__(256, 2) outproj_kernel(
    const float* __restrict__ bo, float* __restrict__ out)
{
    const int m0 = blockIdx.y << 7, n0 = blockIdx.x << 7;
    float acc[4][4][4] = {};
    gemm_body_128(g_A, g_Wo, m0, n0, acc);

    const int lane = threadIdx.x & 31, wid = threadIdx.x >> 5;
    const int wm = wid & 1, wn = wid >> 1;
    #pragma unroll
    for (int mf = 0; mf < 4; ++mf)
        #pragma unroll
        for (int hh = 0; hh < 2; ++hh) {
            int m = m0 + wm*64 + mf*16 + hh*8 + (lane >> 2);
            #pragma unroll
            for (int nf = 0; nf < 4; ++nf) {
                int n = n0 + wn*32 + nf*8 + (lane & 3)*2;
                float2 v = make_float2(acc[mf][nf][hh*2+0] + bo[n],
                                       acc[mf][nf][hh*2+1] + bo[n+1]);
                *(float2*)&out[(size_t)m * EMB + n] = v;
            }
        }
}

// ---------------- flash attention: BQ=128, KV stage = 128 rows, 2-stage -----
// Q/K/P/V all single fp16; P via ex2.f16x2; row sums via ones-MMA.
#define ASP     144
#define KV_BASE 18432
#define V_OFF   18432            // V offset within a KV stage
#define KV_STG  36864            // K(128x144) + V(128x144)
#define ATT_SMEM (KV_BASE + 2*KV_STG)   // 92160
#define SUBOFF  9216             // 64 rows * 144

__global__ void __launch_bounds__(256, 2) attn_kernel()
{
    extern __shared__ char sm[];
    const uint32_t smb = smem_u32(sm);
    const int tid = threadIdx.x, lane = tid & 31, w = tid >> 5;
    const int bh = blockIdx.y, q0 = blockIdx.x << 7;

    const __half* Qh = g_Qh + ((size_t)bh*SEQ + q0)*HD;
    const __half* Kh = g_Kh + (size_t)bh*SEQ*HD;
    const __half* Vh = g_Vh + (size_t)bh*SEQ*HD;

    auto issue_kv = [&](int it) {
        const int kv0 = it << 7;   // 128 kv rows per stage
        const uint32_t sb = smb + KV_BASE + (uint32_t)(it & 1) * KV_STG;
        // 2048 chunks: K 1024 | V 1024 -> 8 per thread
        #pragma unroll
        for (int j = 0; j < 8; ++j) {
            int idx = tid + (j << 8);
            int arr = idx >> 10, c = idx & 1023;
            int row = c >> 3, seg = c & 7;
            size_t ga = (size_t)(kv0 + row)*HD + seg*8;
            const __half* g = (arr == 0) ? Kh : Vh;
            cp16(sb + arr*V_OFF + row*ASP + seg*16, g + ga);
        }
        CP_COMMIT();
    };

    // Q: 128 rows x 8 segs = 1024 chunks -> 4 per thread
    #pragma unroll
    for (int j = 0; j < 4; ++j) {
        int idx = tid + (j << 8);
        int row = idx >> 3, seg = idx & 7;
        cp16(smb + row*ASP + seg*16, Qh + (size_t)row*HD + seg*8);
    }
    CP_COMMIT();
    issue_kv(0);

    float o[8][4] = {};
    float m0_ = __int_as_float(0xff800000), m1_ = m0_;
    float l0_ = 0.f, l1_ = 0.f;

    for (int it = 0; it < SEQ/128; ++it) {
        CP_WAIT(0);
        __syncthreads();
        if (it + 1 < SEQ/128) issue_kv(it + 1);
        const uint32_t stg = smb + KV_BASE + (uint32_t)(it & 1) * KV_STG;

        #pragma unroll
        for (int sub = 0; sub < 2; ++sub) {
            const uint32_t kb = stg + (uint32_t)sub * SUBOFF;  // K rows sub*64..
            const uint32_t vb = stg + V_OFF + (uint32_t)sub * SUBOFF;

            // S = Q K^T
            float s[8][4] = {};
            #pragma unroll
            for (int ks = 0; ks < 4; ++ks) {
                uint32_t aQ[4], bF[4][4];
                uint32_t qrow = w*16 + ((lane>>3)&1)*8 + (lane&7);
                uint32_t qcol = ks*32 + ((lane>>4)&1)*16;
                ldsm4(aQ, smb + qrow*ASP + qcol);
                #pragma unroll
                for (int ng = 0; ng < 4; ++ng) {
                    uint32_t krow = ng*16 + ((lane>>4)&1)*8 + (lane&7);
                    uint32_t kcol = ks*32 + ((lane>>3)&1)*16;
                    ldsm4(bF[ng], kb + krow*ASP + kcol);
                }
                #pragma unroll
                for (int ng = 0; ng < 4; ++ng) {
                    mma_h(s[2*ng],   aQ, bF[ng][0], bF[ng][1]);
                    mma_h(s[2*ng+1], aQ, bF[ng][2], bF[ng][3]);
                }
            }

            // online softmax (rows lane>>2 and +8); sums via ones-MMA
            float mx0 = fmaxf(s[0][0], s[0][1]), mx1 = fmaxf(s[0][2], s[0][3]);
            #pragma unroll
            for (int j = 1; j < 8; ++j) {
                mx0 = fmaxf(mx0, fmaxf(s[j][0], s[j][1]));
                mx1 = fmaxf(mx1, fmaxf(s[j][2], s[j][3]));
            }
            mx0 = fmaxf(mx0, __shfl_xor_sync(0xffffffffu, mx0, 1));
            mx0 = fmaxf(mx0, __shfl_xor_sync(0xffffffffu, mx0, 2));
            mx1 = fmaxf(mx1, __shfl_xor_sync(0xffffffffu, mx1, 1));
            mx1 = fmaxf(mx1, __shfl_xor_sync(0xffffffffu, mx1, 2));
            float mn0 = fmaxf(m0_, mx0), mn1 = fmaxf(m1_, mx1);
            float c0 = exp2f(m0_ - mn0), c1 = exp2f(m1_ - mn1);
            m0_ = mn0; m1_ = mn1;
            #pragma unroll
            for (int j = 0; j < 8; ++j) {
                o[j][0] *= c0; o[j][1] *= c0; o[j][2] *= c1; o[j][3] *= c1;
            }

            // O += P V ; l += P @ ones.
            float lacc[4] = {};
            #pragma unroll
            for (int ks = 0; ks < 4; ++ks) {
                uint32_t aP[4];
                aP[0] = ex2h2(packh(s[2*ks][0]   - mn0, s[2*ks][1]   - mn0));
                aP[1] = ex2h2(packh(s[2*ks][2]   - mn1, s[2*ks][3]   - mn1));
                aP[2] = ex2h2(packh(s[2*ks+1][0] - mn0, s[2*ks+1][1] - mn0));
                aP[3] = ex2h2(packh(s[2*ks+1][2] - mn1, s[2*ks+1][3] - mn1));
                mma_h(lacc, aP, ONESH2, ONESH2);
                #pragma unroll
                for (int ng = 0; ng < 4; ++ng) {
                    uint32_t bH[4];
                    uint32_t vrow = ks*16 + ((lane>>3)&1)*8 + (lane&7);
                    uint32_t vcol = ng*32 + ((lane>>4)&1)*16;
                    ldsm4t(bH, vb + vrow*ASP + vcol);
                    mma_h(o[2*ng],   aP, bH[0], bH[1]);
                    mma_h(o[2*ng+1], aP, bH[2], bH[3]);
                }
            }
            l0_ = l0_ * c0 + lacc[0];
            l1_ = l1_ * c1 + lacc[2];
        }
        __syncthreads();
    }

    // epilogue -> single fp16 A in [B*S][EMB]
    const int b = bh >> 4, h = bh & 15;
    float inv0 = 1.0f / l0_, inv1 = 1.0f / l1_;
    const int r0 = q0 + w*16 + (lane >> 2), r1 = r0 + 8;
    #pragma unroll
    for (int nf = 0; nf < 8; ++nf) {
        int d = nf*8 + (lane & 3)*2;
        int e = h*HD + d;
        *(uint32_t*)(g_A + ((size_t)(b*SEQ + r0))*EMB + e) = packh(o[nf][0]*inv0, o[nf][1]*inv0);
        *(uint32_t*)(g_A + ((size_t)(b*SEQ + r1))*EMB + e) = packh(o[nf][2]*inv1, o[nf][3]*inv1);
    }
}

// ---------------------------------------------------------------------------
extern "C" void kernel_launch(void* const* d_in, const int* in_sizes, int n_in,
                              void* d_out, int out_size)
{
    (void)in_sizes; (void)n_in; (void)out_size;
    const float* x  = (const float*)d_in[0];
    const float* Wq = (const float*)d_in[1];
    const float* bq = (const float*)d_in[2];
    const float* Wk = (const float*)d_in[3];
    const float* bk = (const float*)d_in[4];
    const float* Wv = (const float*)d_in[5];
    const float* bv = (const float*)d_in[6];
    const float* Wo = (const float*)d_in[7];
    const float* bo = (const float*)d_in[8];
    float* out = (float*)d_out;

    cudaFuncSetAttribute(qkv_kernel,     cudaFuncAttributeMaxDynamicSharedMemorySize, GEMM_SMEM);
    cudaFuncSetAttribute(outproj_kernel, cudaFuncAttributeMaxDynamicSharedMemorySize, GEMM_SMEM);
    cudaFuncSetAttribute(attn_kernel,    cudaFuncAttributeMaxDynamicSharedMemorySize, ATT_SMEM);

    split_all_kernel<<<4096, 256>>>(x, Wq, Wk, Wv, Wo);

    dim3 gqkv(EMB/128, MTOK/128, 3);     // 8 x 32 x 3 = 768 CTAs
    qkv_kernel<<<gqkv, 256, GEMM_SMEM>>>(bq, bk, bv);

    dim3 gattn(SEQ/128, BHN);            // 16 x 32 = 512 CTAs
    attn_kernel<<<gattn, 256, ATT_SMEM>>>();

    dim3 gout(EMB/128, MTOK/128);        // 8 x 32 = 256
    outproj_kernel<<<gout, 256, GEMM_SMEM>>>(bo, out);
}

// round 17
// speedup vs baseline: 1.2690x; 1.0103x over previous
#include <cuda_runtime.h>
#include <cuda_fp16.h>
#include <cstdint>

#define EMB   1024
#define NH    16
#define HD    64
#define BATCH 2
#define SEQ   2048
#define MTOK  (BATCH*SEQ)   // 4096
#define BHN   (BATCH*NH)    // 32

// ---------------- scratch (__device__ globals; no allocs allowed) -----------
__device__ __half g_Xh[(size_t)MTOK*EMB];
__device__ __half g_A[(size_t)MTOK*EMB];
__device__ __half g_Qh[(size_t)MTOK*EMB];
__device__ __half g_Kh[(size_t)MTOK*EMB];
__device__ __half g_Vh[(size_t)MTOK*EMB];
__device__ __half g_Wq[(size_t)EMB*EMB], g_Wk[(size_t)EMB*EMB];
__device__ __half g_Wv[(size_t)EMB*EMB], g_Wo[(size_t)EMB*EMB];

// ---------------- helpers ---------------------------------------------------
__device__ __forceinline__ uint32_t smem_u32(const void* p) {
    uint32_t a;
    asm("{ .reg .u64 t; cvta.to.shared.u64 t, %1; cvt.u32.u64 %0, t; }" : "=r"(a) : "l"(p));
    return a;
}
__device__ __forceinline__ void cp16(uint32_t d, const void* s) {
    asm volatile("cp.async.cg.shared.global [%0], [%1], 16;" :: "r"(d), "l"(s));
}
#define CP_COMMIT() asm volatile("cp.async.commit_group;")
#define CP_WAIT(n)  asm volatile("cp.async.wait_group %0;" :: "n"(n))

__device__ __forceinline__ void ldsm4(uint32_t (&r)[4], uint32_t a) {
    asm volatile("ldmatrix.sync.aligned.m8n8.x4.shared.b16 {%0,%1,%2,%3}, [%4];"
        : "=r"(r[0]), "=r"(r[1]), "=r"(r[2]), "=r"(r[3]) : "r"(a));
}
__device__ __forceinline__ void ldsm4t(uint32_t (&r)[4], uint32_t a) {
    asm volatile("ldmatrix.sync.aligned.m8n8.x4.trans.shared.b16 {%0,%1,%2,%3}, [%4];"
        : "=r"(r[0]), "=r"(r[1]), "=r"(r[2]), "=r"(r[3]) : "r"(a));
}
__device__ __forceinline__ void mma_h(float (&c)[4], const uint32_t (&a)[4], uint32_t b0, uint32_t b1) {
    asm("mma.sync.aligned.m16n8k16.row.col.f32.f16.f16.f32 "
        "{%0,%1,%2,%3}, {%4,%5,%6,%7}, {%8,%9}, {%0,%1,%2,%3};"
        : "+f"(c[0]), "+f"(c[1]), "+f"(c[2]), "+f"(c[3])
        : "r"(a[0]), "r"(a[1]), "r"(a[2]), "r"(a[3]), "r"(b0), "r"(b1));
}
__device__ __forceinline__ uint32_t packh(float v0, float v1) {
    __half2 h = __floats2half2_rn(v0, v1);
    return *(uint32_t*)&h;
}
__device__ __forceinline__ uint32_t ex2h2(uint32_t x) {
    uint32_t r;
    asm("ex2.approx.f16x2 %0, %1;" : "=r"(r) : "r"(x));
    return r;
}
#define ONESH2 0x3C003C00u   // half2(1.0, 1.0)

// ---------------- fused fp32 -> fp16 pack (all 5 tensors) --------------------
__global__ __launch_bounds__(256) void split_all_kernel(
    const float* __restrict__ x,  const float* __restrict__ wq,
    const float* __restrict__ wk, const float* __restrict__ wv,
    const float* __restrict__ wo)
{
    int i = blockIdx.x * 256 + threadIdx.x;
    const float* src; __half* dst; int off;
    if (i < 524288) { src = x; dst = g_Xh; off = i; }
    else {
        int j = i - 524288;
        int w = j >> 17;
        off = j & 131071;
        if (w == 0)      { src = wq; dst = g_Wq; }
        else if (w == 1) { src = wk; dst = g_Wk; }
        else if (w == 2) { src = wv; dst = g_Wv; }
        else             { src = wo; dst = g_Wo; }
    }
    float4 a = ((const float4*)src)[2*off];
    float4 b = ((const float4*)src)[2*off + 1];
    uint32_t hp[4];
    hp[0] = packh(a.x, a.y); hp[1] = packh(a.z, a.w);
    hp[2] = packh(b.x, b.y); hp[3] = packh(b.z, b.w);
    ((uint4*)dst)[off] = make_uint4(hp[0], hp[1], hp[2], hp[3]);
}

// ---------------- GEMM body: 128x128 CTA, BK=64, 2-stage, 2 CTA/SM ----------
#define SPAD   144
#define B_OFF  18432
#define STG    36864
#define GEMM_SMEM (2*STG)   // 73728
#define NITER (EMB/64)      // 16

__device__ __forceinline__ void gemm_body_128(
    const __half* __restrict__ Ah, const __half* __restrict__ Wh,
    int m0, int n0, float (&acc)[4][4][4])
{
    extern __shared__ char sm[];
    const uint32_t smb = smem_u32(sm);
    const int tid = threadIdx.x, lane = tid & 31, wid = tid >> 5;
    const int wm = wid & 1, wn = wid >> 1;

    auto issue = [&](int it) {
        const int k0 = it << 6;
        const uint32_t sb = smb + (uint32_t)(it & 1) * STG;
        #pragma unroll
        for (int j = 0; j < 8; ++j) {
            int idx = tid + (j << 8);
            if (idx < 1024) {
                int row = idx >> 3, seg = idx & 7;
                cp16(sb + row*SPAD + seg*16, Ah + (size_t)(m0 + row)*EMB + k0 + seg*8);
            } else {
                int c = idx - 1024, row = c >> 3, seg = c & 7;
                cp16(sb + B_OFF + row*SPAD + seg*16, Wh + (size_t)(n0 + row)*EMB + k0 + seg*8);
            }
        }
        CP_COMMIT();
    };

    issue(0);
    for (int it = 0; it < NITER; ++it) {
        CP_WAIT(0);
        __syncthreads();
        if (it + 1 < NITER) issue(it + 1);
        const uint32_t sb = smb + (uint32_t)(it & 1) * STG;
        #pragma unroll
        for (int ks = 0; ks < 4; ++ks) {
            uint32_t aH[4][4], bF[2][4];
            uint32_t acol = ks*32 + ((lane>>4)&1)*16;
            #pragma unroll
            for (int mf = 0; mf < 4; ++mf) {
                uint32_t row = wm*64 + mf*16 + ((lane>>3)&1)*8 + (lane&7);
                ldsm4(aH[mf], sb + row*SPAD + acol);
            }
            #pragma unroll
            for (int ng = 0; ng < 2; ++ng) {
                uint32_t row = wn*32 + ng*16 + ((lane>>4)&1)*8 + (lane&7);
                uint32_t col = ks*32 + ((lane>>3)&1)*16;
                ldsm4(bF[ng], sb + B_OFF + row*SPAD + col);
            }
            #pragma unroll
            for (int ng = 0; ng < 2; ++ng)
                #pragma unroll
                for (int mf = 0; mf < 4; ++mf) {
                    mma_h(acc[mf][2*ng],   aH[mf], bF[ng][0], bF[ng][1]);
                    mma_h(acc[mf][2*ng+1], aH[mf], bF[ng][2], bF[ng][3]);
                }
        }
        // no trailing sync: top-of-loop barrier of the next iteration already
        // orders this iteration's reads before issue(it+2) rewrites the stage
    }
}

// ---------------- QKV projection (all single-term) ---------------------------
__global__ void __launch_bounds__(256, 2) qkv_kernel(
    const float* __restrict__ bq, const float* __restrict__ bk, const float* __restrict__ bv)
{
    const __half* Wh; const float* bias; __half* dh; float alpha;
    if (blockIdx.z == 0)      { Wh = g_Wq; bias = bq; dh = g_Qh; alpha = 0.18033688011112042f; }
    else if (blockIdx.z == 1) { Wh = g_Wk; bias = bk; dh = g_Kh; alpha = 1.0f; }
    else                      { Wh = g_Wv; bias = bv; dh = g_Vh; alpha = 1.0f; }

    const int m0 = blockIdx.y << 7, n0 = blockIdx.x << 7;
    float acc[4][4][4] = {};
    gemm_body_128(g_Xh, Wh, m0, n0, acc);

    const int lane = threadIdx.x & 31, wid = threadIdx.x >> 5;
    const int wm = wid & 1, wn = wid >> 1;
    #pragma unroll
    for (int mf = 0; mf < 4; ++mf)
        #pragma unroll
        for (int hh = 0; hh < 2; ++hh) {
            int m = m0 + wm*64 + mf*16 + hh*8 + (lane >> 2);
            int b = m >> 11, s = m & (SEQ-1);
            #pragma unroll
            for (int nf = 0; nf < 4; ++nf) {
                int n = n0 + wn*32 + nf*8 + (lane & 3)*2;
                int h = n >> 6, d = n & 63;
                float v0 = (acc[mf][nf][hh*2+0] + bias[n])   * alpha;
                float v1 = (acc[mf][nf][hh*2+1] + bias[n+1]) * alpha;
                size_t o = ((size_t)(b*NH + h)*SEQ + s)*HD + d;
                *(uint32_t*)(dh + o) = packh(v0, v1);
            }
        }
}

// ---------------- output projection -----------------------------------------
__global__ void __launch_bounds__(256, 2) outproj_kernel(
    const float* __restrict__ bo, float* __restrict__ out)
{
    const int m0 = blockIdx.y << 7, n0 = blockIdx.x << 7;
    float acc[4][4][4] = {};
    gemm_body_128(g_A, g_Wo, m0, n0, acc);

    const int lane = threadIdx.x & 31, wid = threadIdx.x >> 5;
    const int wm = wid & 1, wn = wid >> 1;
    #pragma unroll
    for (int mf = 0; mf < 4; ++mf)
        #pragma unroll
        for (int hh = 0; hh < 2; ++hh) {
            int m = m0 + wm*64 + mf*16 + hh*8 + (lane >> 2);
            #pragma unroll
            for (int nf = 0; nf < 4; ++nf) {
                int n = n0 + wn*32 + nf*8 + (lane & 3)*2;
                float2 v = make_float2(acc[mf][nf][hh*2+0] + bo[n],
                                       acc[mf][nf][hh*2+1] + bo[n+1]);
                *(float2*)&out[(size_t)m * EMB + n] = v;
            }
        }
}

// ---------------- flash attention: BQ=128, KV stage 128 rows, 2-stage -------
// Exact online softmax (running max), P via ex2.f16x2 with small args,
// row sums via ones-MMA. Rescale is SKIPPED when the max doesn't move
// (c==1.0 exactly -> identity; bit-identical to always-rescale).
#define ASP     144
#define KV_BASE 18432
#define V_OFF   18432
#define KV_STG  36864
#define ATT_SMEM (KV_BASE + 2*KV_STG)   // 92160
#define SUBOFF  9216

__global__ void __launch_bounds__(256, 2) attn_kernel()
{
    extern __shared__ char sm[];
    const uint32_t smb = smem_u32(sm);
    const int tid = threadIdx.x, lane = tid & 31, w = tid >> 5;
    const int bh = blockIdx.y, q0 = blockIdx.x << 7;

    const __half* Qh = g_Qh + ((size_t)bh*SEQ + q0)*HD;
    const __half* Kh = g_Kh + (size_t)bh*SEQ*HD;
    const __half* Vh = g_Vh + (size_t)bh*SEQ*HD;

    auto issue_kv = [&](int it) {
        const int kv0 = it << 7;
        const uint32_t sb = smb + KV_BASE + (uint32_t)(it & 1) * KV_STG;
        #pragma unroll
        for (int j = 0; j < 8; ++j) {
            int idx = tid + (j << 8);
            int arr = idx >> 10, c = idx & 1023;
            int row = c >> 3, seg = c & 7;
            size_t ga = (size_t)(kv0 + row)*HD + seg*8;
            const __half* g = (arr == 0) ? Kh : Vh;
            cp16(sb + arr*V_OFF + row*ASP + seg*16, g + ga);
        }
        CP_COMMIT();
    };

    #pragma unroll
    for (int j = 0; j < 4; ++j) {
        int idx = tid + (j << 8);
        int row = idx >> 3, seg = idx & 7;
        cp16(smb + row*ASP + seg*16, Qh + (size_t)row*HD + seg*8);
    }
    CP_COMMIT();
    issue_kv(0);

    float o[8][4] = {};
    float m0_ = __int_as_float(0xff800000), m1_ = m0_;
    float l0_ = 0.f, l1_ = 0.f;

    for (int it = 0; it < SEQ/128; ++it) {
        CP_WAIT(0);
        __syncthreads();
        if (it + 1 < SEQ/128) issue_kv(it + 1);
        const uint32_t stg = smb + KV_BASE + (uint32_t)(it & 1) * KV_STG;

        #pragma unroll
        for (int sub = 0; sub < 2; ++sub) {
            const uint32_t kb = stg + (uint32_t)sub * SUBOFF;
            const uint32_t vb = stg + V_OFF + (uint32_t)sub * SUBOFF;

            // S = Q K^T
            float s[8][4] = {};
            #pragma unroll
            for (int ks = 0; ks < 4; ++ks) {
                uint32_t aQ[4], bF[4][4];
                uint32_t qrow = w*16 + ((lane>>3)&1)*8 + (lane&7);
                uint32_t qcol = ks*32 + ((lane>>4)&1)*16;
                ldsm4(aQ, smb + qrow*ASP + qcol);
                #pragma unroll
                for (int ng = 0; ng < 4; ++ng) {
                    uint32_t krow = ng*16 + ((lane>>4)&1)*8 + (lane&7);
                    uint32_t kcol = ks*32 + ((lane>>3)&1)*16;
                    ldsm4(bF[ng], kb + krow*ASP + kcol);
                }
                #pragma unroll
                for (int ng = 0; ng < 4; ++ng) {
                    mma_h(s[2*ng],   aQ, bF[ng][0], bF[ng][1]);
                    mma_h(s[2*ng+1], aQ, bF[ng][2], bF[ng][3]);
                }
            }

            // online softmax max-tracking; rescale only when max moves
            float mx0 = fmaxf(s[0][0], s[0][1]), mx1 = fmaxf(s[0][2], s[0][3]);
            #pragma unroll
            for (int j = 1; j < 8; ++j) {
                mx0 = fmaxf(mx0, fmaxf(s[j][0], s[j][1]));
                mx1 = fmaxf(mx1, fmaxf(s[j][2], s[j][3]));
            }
            mx0 = fmaxf(mx0, __shfl_xor_sync(0xffffffffu, mx0, 1));
            mx0 = fmaxf(mx0, __shfl_xor_sync(0xffffffffu, mx0, 2));
            mx1 = fmaxf(mx1, __shfl_xor_sync(0xffffffffu, mx1, 1));
            mx1 = fmaxf(mx1, __shfl_xor_sync(0xffffffffu, mx1, 2));
            if (mx0 > m0_) {
                float c0 = exp2f(m0_ - mx0);
                m0_ = mx0;
                l0_ *= c0;
                #pragma unroll
                for (int j = 0; j < 8; ++j) { o[j][0] *= c0; o[j][1] *= c0; }
            }
            if (mx1 > m1_) {
                float c1 = exp2f(m1_ - mx1);
                m1_ = mx1;
                l1_ *= c1;
                #pragma unroll
                for (int j = 0; j < 8; ++j) { o[j][2] *= c1; o[j][3] *= c1; }
            }
            float mn0 = m0_, mn1 = m1_;

            // O += P V ; l += P @ ones.  P = ex2(s - mn) in fp16x2.
            float lacc[4] = {};
            #pragma unroll
            for (int ks = 0; ks < 4; ++ks) {
                uint32_t aP[4];
                aP[0] = ex2h2(packh(s[2*ks][0]   - mn0, s[2*ks][1]   - mn0));
                aP[1] = ex2h2(packh(s[2*ks][2]   - mn1, s[2*ks][3]   - mn1));
                aP[2] = ex2h2(packh(s[2*ks+1][0] - mn0, s[2*ks+1][1] - mn0));
                aP[3] = ex2h2(packh(s[2*ks+1][2] - mn1, s[2*ks+1][3] - mn1));
                mma_h(lacc, aP, ONESH2, ONESH2);
                #pragma unroll
                for (int ng = 0; ng < 4; ++ng) {
                    uint32_t bH[4];
                    uint32_t vrow = ks*16 + ((lane>>3)&1)*8 + (lane&7);
                    uint32_t vcol = ng*32 + ((lane>>4)&1)*16;
                    ldsm4t(bH, vb + vrow*ASP + vcol);
                    mma_h(o[2*ng],   aP, bH[0], bH[1]);
                    mma_h(o[2*ng+1], aP, bH[2], bH[3]);
                }
            }
            l0_ += lacc[0];
            l1_ += lacc[2];
        }
        // no trailing sync: next iteration's top barrier orders stage reuse
    }

    // epilogue -> single fp16 A in [B*S][EMB]
    const int b = bh >> 4, h = bh & 15;
    float inv0 = 1.0f / l0_, inv1 = 1.0f / l1_;
    const int r0 = q0 + w*16 + (lane >> 2), r1 = r0 + 8;
    #pragma unroll
    for (int nf = 0; nf < 8; ++nf) {
        int d = nf*8 + (lane & 3)*2;
        int e = h*HD + d;
        *(uint32_t*)(g_A + ((size_t)(b*SEQ + r0))*EMB + e) = packh(o[nf][0]*inv0, o[nf][1]*inv0);
        *(uint32_t*)(g_A + ((size_t)(b*SEQ + r1))*EMB + e) = packh(o[nf][2]*inv1, o[nf][3]*inv1);
    }
}

// ---------------------------------------------------------------------------
extern "C" void kernel_launch(void* const* d_in, const int* in_sizes, int n_in,
                              void* d_out, int out_size)
{
    (void)in_sizes; (void)n_in; (void)out_size;
    const float* x  = (const float*)d_in[0];
    const float* Wq = (const float*)d_in[1];
    const float* bq = (const float*)d_in[2];
    const float* Wk = (const float*)d_in[3];
    const float* bk = (const float*)d_in[4];
    const float* Wv = (const float*)d_in[5];
    const float* bv = (const float*)d_in[6];
    const float* Wo = (const float*)d_in[7];
    const float* bo = (const float*)d_in[8];
    float* out = (float*)d_out;

    cudaFuncSetAttribute(qkv_kernel,     cudaFuncAttributeMaxDynamicSharedMemorySize, GEMM_SMEM);
    cudaFuncSetAttribute(outproj_kernel, cudaFuncAttributeMaxDynamicSharedMemorySize, GEMM_SMEM);
    cudaFuncSetAttribute(attn_kernel,    cudaFuncAttributeMaxDynamicSharedMemorySize, ATT_SMEM);

    split_all_kernel<<<4096, 256>>>(x, Wq, Wk, Wv, Wo);

    dim3 gqkv(EMB/128, MTOK/128, 3);     // 768 CTAs
    qkv_kernel<<<gqkv, 256, GEMM_SMEM>>>(bq, bk, bv);

    dim3 gattn(SEQ/128, BHN);            // 512 CTAs
    attn_kernel<<<gattn, 256, ATT_SMEM>>>();

    dim3 gout(EMB/128, MTOK/128);        // 256 CTAs
    outproj_kernel<<<gout, 256, GEMM_SMEM>>>(bo, out);
}